// round 13
// baseline (speedup 1.0000x reference)
#include <cuda_runtime.h>
#include <cuda_bf16.h>
#include <cstddef>
#include <cstdint>

#define HDIM 1024
#define SLEN 4096
#define BATCH 32
#define NSB 8                              // s-blocks per batch = cluster size
#define ROWS_PER_BLOCK (SLEN / NSB)        // 512
#define NWARPS 8
#define ROWS_PER_WARP (ROWS_PER_BLOCK / NWARPS)  // 64
#define NSTAGE 3                           // cp.async ring depth per warp

// dynamic smem layout (bytes)
#define SMEM_KEYS_OFF   0                          // 8 warps * 3 slots * 4096
#define SMEM_KEYS_BYTES (NWARPS * NSTAGE * 4096)   // 98304
#define SMEM_SCORES_OFF SMEM_KEYS_BYTES            // 2048
#define SMEM_BACC_OFF   (SMEM_SCORES_OFF + 2048)   // 4096
#define SMEM_MISC_OFF   (SMEM_BACC_OFF + 4096)     // 256
#define SMEM_TOTAL      (SMEM_MISC_OFF + 256)      // 104960... (see static_assert)

// Scratch (device globals; no allocation in kernel_launch)
__device__ float g_vprime[HDIM];                   // U^T V

// ---------------- smem / cluster / cp.async helpers ----------------
__device__ __forceinline__ uint32_t smem_u32(const void* p) {
    return (uint32_t)__cvta_generic_to_shared(p);
}
__device__ __forceinline__ uint32_t mapa_rank(uint32_t addr, uint32_t rank) {
    uint32_t r;
    asm("mapa.shared::cluster.u32 %0, %1, %2;" : "=r"(r) : "r"(addr), "r"(rank));
    return r;
}
__device__ __forceinline__ float2 ld_dsmem_f2(uint32_t a) {
    float2 v;
    asm volatile("ld.shared::cluster.v2.f32 {%0,%1}, [%2];"
                 : "=f"(v.x), "=f"(v.y) : "r"(a));
    return v;
}
__device__ __forceinline__ float4 ld_dsmem_f4(uint32_t a) {
    float4 v;
    asm volatile("ld.shared::cluster.v4.f32 {%0,%1,%2,%3}, [%4];"
                 : "=f"(v.x), "=f"(v.y), "=f"(v.z), "=f"(v.w) : "r"(a));
    return v;
}
__device__ __forceinline__ float4 lds_f4(uint32_t a) {
    float4 v;
    asm volatile("ld.shared.v4.f32 {%0,%1,%2,%3}, [%4];"
                 : "=f"(v.x), "=f"(v.y), "=f"(v.z), "=f"(v.w) : "r"(a));
    return v;
}
#define CP_ASYNC16(dst, src) \
    asm volatile("cp.async.cg.shared.global [%0], [%1], 16;" \
                 :: "r"(dst), "l"(src))
#define CP_COMMIT()  asm volatile("cp.async.commit_group;" ::: "memory")
#define CP_WAIT(n)   asm volatile("cp.async.wait_group %0;" :: "n"(n) : "memory")
#define CLUSTER_ARRIVE() asm volatile("barrier.cluster.arrive.aligned;" ::: "memory")
#define CLUSTER_WAIT()   asm volatile("barrier.cluster.wait.aligned;" ::: "memory")
#define CLUSTER_SYNC() do { CLUSTER_ARRIVE(); CLUSTER_WAIT(); } while (0)

// ---------------------------------------------------------------------------
// K1 (fused): v'[h] = sum_o U[o,h] * V[o]. grid 128, block 256. PDL trigger.
// ---------------------------------------------------------------------------
__global__ void vprime_fused_kernel(const float* __restrict__ U,
                                    const float* __restrict__ V) {
    const int t     = threadIdx.x;
    const int h_off = t & 7;
    const int o_idx = t >> 3;              // 0..31
    const int h0    = blockIdx.x * 8;

    __shared__ float sm[256];

    float acc = 0.0f;
#pragma unroll 8
    for (int it = 0; it < 32; it++) {
        const int o = it * 32 + o_idx;
        acc += U[(size_t)o * HDIM + h0 + h_off] * __ldg(&V[o]);
    }
    sm[t] = acc;
    __syncthreads();

#pragma unroll
    for (int s = 128; s >= 8; s >>= 1) {
        if (t < s) sm[t] += sm[t + s];
        __syncthreads();
    }
    if (t < 8) g_vprime[h0 + t] = sm[t];

#if __CUDA_ARCH__ >= 900
    cudaTriggerProgrammaticLaunchCompletion();
#endif
}

// ---------------------------------------------------------------------------
// K2: streaming pass with cp.async 3-deep per-warp row pipeline (keys read
// once, L1-bypass). v' in registers (keys no longer need register buffers).
// In-flight bytes/warp 16KB -> request capacity > HBM share even on 1-CTA
// SMs. Key ring smem is aliased for the warp-partials merge afterwards.
// Cluster (NSB,1,1) epilogue via DSMEM; PDL entry. grid (NSB,BATCH), 256 thr.
// out layout: [context B*H | weight B*S]
// ---------------------------------------------------------------------------
__global__ void __launch_bounds__(256, 2) __cluster_dims__(NSB, 1, 1)
main_pass_kernel(const float* __restrict__ keys, float* __restrict__ out) {
    extern __shared__ __align__(16) char dynsmem[];

    const int b    = blockIdx.y;
    const int sb   = blockIdx.x;          // == cluster rank
    const int w    = threadIdx.x >> 5;
    const int lane = threadIdx.x & 31;
    const int t    = threadIdx.x;

    float*  s_scores = reinterpret_cast<float*>(dynsmem + SMEM_SCORES_OFF);
    float4* s_bacc   = reinterpret_cast<float4*>(dynsmem + SMEM_BACC_OFF);
    float*  s_m      = reinterpret_cast<float*>(dynsmem + SMEM_MISC_OFF);        // [8]
    float*  s_l      = s_m + NWARPS;                                             // [8]
    float2* s_ml     = reinterpret_cast<float2*>(s_l + NWARPS);                  // 1
    float*  s_pm     = reinterpret_cast<float*>(s_ml + 1);                       // [8]
    float*  s_pl     = s_pm + NSB;                                               // [8]

#if __CUDA_ARCH__ >= 900
    cudaGridDependencySynchronize();
#endif
    // v' into registers: lane covers float4 index i*32+lane
    float4 vp[8];
#pragma unroll
    for (int i = 0; i < 8; i++)
        vp[i] = __ldg(reinterpret_cast<const float4*>(g_vprime) + i * 32 + lane);

    float m = -3.0e38f;
    float l = 0.0f;
    float4 acc[8];
#pragma unroll
    for (int i = 0; i < 8; i++) acc[i] = make_float4(0.f, 0.f, 0.f, 0.f);

    const int s0 = sb * ROWS_PER_BLOCK + w * ROWS_PER_WARP;
    const float4* __restrict__ gbase =
        reinterpret_cast<const float4*>(keys + (size_t)b * SLEN * HDIM)
        + (size_t)s0 * (HDIM / 4) + lane;
    // per-warp ring: 3 slots of 4KB; this lane's 16B column
    const uint32_t ring_base =
        smem_u32(dynsmem) + (uint32_t)w * (NSTAGE * 4096) + (uint32_t)lane * 16;
    float* __restrict__ w_scores = &s_scores[w * ROWS_PER_WARP];

    // prologue: fill 3 stages
#pragma unroll
    for (int r = 0; r < NSTAGE; r++) {
        const float4* __restrict__ src = gbase + (size_t)r * (HDIM / 4);
        const uint32_t dst = ring_base + (uint32_t)r * 4096;
#pragma unroll
        for (int i = 0; i < 8; i++) CP_ASYNC16(dst + i * 512, src + i * 32);
        CP_COMMIT();
    }

    int slot = 0;
    for (int j = 0; j < ROWS_PER_WARP; j++) {
        CP_WAIT(NSTAGE - 1);               // group j complete

        const uint32_t sl = ring_base + (uint32_t)slot * 4096;
        float4 k[8];
#pragma unroll
        for (int i = 0; i < 8; i++) k[i] = lds_f4(sl + (uint32_t)(i * 512));

        float d = 0.0f;
#pragma unroll
        for (int i = 0; i < 8; i++) {
            d += k[i].x * vp[i].x + k[i].y * vp[i].y +
                 k[i].z * vp[i].z + k[i].w * vp[i].w;
        }
#pragma unroll
        for (int off = 16; off; off >>= 1)
            d += __shfl_xor_sync(0xffffffffu, d, off);

        // refill this slot with row j+3 (registers k[] already hold row j)
        if (j + NSTAGE < ROWS_PER_WARP) {
            const float4* __restrict__ src =
                gbase + (size_t)(j + NSTAGE) * (HDIM / 4);
#pragma unroll
            for (int i = 0; i < 8; i++) CP_ASYNC16(sl + i * 512, src + i * 32);
        }
        CP_COMMIT();                       // keep group count in lockstep

        if (lane == 0) w_scores[j] = d;

        if (d > m) {              // warp-uniform, rare
            const float sc = __expf(m - d);
            l *= sc;
#pragma unroll
            for (int i = 0; i < 8; i++) {
                acc[i].x *= sc; acc[i].y *= sc;
                acc[i].z *= sc; acc[i].w *= sc;
            }
            m = d;
        }
        const float p = __expf(d - m);
        l += p;
#pragma unroll
        for (int i = 0; i < 8; i++) {
            acc[i].x += p * k[i].x; acc[i].y += p * k[i].y;
            acc[i].z += p * k[i].z; acc[i].w += p * k[i].w;
        }

        slot = (slot + 1 == NSTAGE) ? 0 : slot + 1;
    }
    CP_WAIT(0);
    __syncthreads();                       // ring dead; alias as s_acc below

    // ---- block-level merge of 8 warp partials (aliased smem) ----
    float4 (*s_acc)[256] = reinterpret_cast<float4(*)[256]>(dynsmem);
#pragma unroll
    for (int i = 0; i < 8; i++) s_acc[w][i * 32 + lane] = acc[i];
    if (lane == 0) { s_m[w] = m; s_l[w] = l; }
    __syncthreads();

    float Mb = s_m[0];
#pragma unroll
    for (int ww = 1; ww < NWARPS; ww++) Mb = fmaxf(Mb, s_m[ww]);
    float Lb = 0.0f;
    float scale[NWARPS];
#pragma unroll
    for (int ww = 0; ww < NWARPS; ww++) {
        scale[ww] = __expf(s_m[ww] - Mb);
        Lb += scale[ww] * s_l[ww];
    }

    float4 bsum = make_float4(0.f, 0.f, 0.f, 0.f);
#pragma unroll
    for (int ww = 0; ww < NWARPS; ww++) {
        float4 v = s_acc[ww][t];
        const float sc = scale[ww];
        bsum.x += sc * v.x; bsum.y += sc * v.y;
        bsum.z += sc * v.z; bsum.w += sc * v.w;
    }
    s_bacc[t] = bsum;
    if (t == 0) { s_ml->x = Mb; s_ml->y = Lb; }
    __syncthreads();

    // ---- cluster-wide merge via DSMEM ----
    CLUSTER_SYNC();

    if (t < NSB) {
        uint32_t a = mapa_rank(smem_u32(s_ml), (uint32_t)t);
        float2 ml = ld_dsmem_f2(a);
        s_pm[t] = ml.x; s_pl[t] = ml.y;
    }
    __syncthreads();

    float M = s_pm[0];
#pragma unroll
    for (int p = 1; p < NSB; p++) M = fmaxf(M, s_pm[p]);
    float L = 0.0f;
    float scg[NSB];
#pragma unroll
    for (int p = 0; p < NSB; p++) {
        scg[p] = __expf(s_pm[p] - M);
        L += scg[p] * s_pl[p];
    }
    const float invL = 1.0f / L;

    // context slice: this CTA owns float4 columns [sb*32, sb*32+32)
    if (t < 32) {
        const int h4 = sb * 32 + t;
        const uint32_t loc = smem_u32(&s_bacc[h4]);
        float4 cs = make_float4(0.f, 0.f, 0.f, 0.f);
#pragma unroll
        for (int p = 0; p < NSB; p++) {
            float4 v = ld_dsmem_f4(mapa_rank(loc, (uint32_t)p));
            cs.x += scg[p] * v.x; cs.y += scg[p] * v.y;
            cs.z += scg[p] * v.z; cs.w += scg[p] * v.w;
        }
        cs.x *= invL; cs.y *= invL; cs.z *= invL; cs.w *= invL;
        reinterpret_cast<float4*>(out + (size_t)b * HDIM)[h4] = cs;
    }

    // all cross-CTA reads done
    CLUSTER_ARRIVE();

    // weights for this CTA's 512 rows — overlaps peers' epilogues
    float* __restrict__ wout =
        out + (size_t)BATCH * HDIM + (size_t)b * SLEN + (size_t)sb * ROWS_PER_BLOCK;
#pragma unroll
    for (int i = 0; i < ROWS_PER_BLOCK / 256; i++) {
        const int s = i * 256 + t;
        wout[s] = __expf(s_scores[s] - M) * invL;
    }

    // keep SMEM alive until all peers finished their DSMEM reads
    CLUSTER_WAIT();
}

// ---------------------------------------------------------------------------
extern "C" void kernel_launch(void* const* d_in, const int* in_sizes, int n_in,
                              void* d_out, int out_size) {
    // inputs (metadata order): query, keys, W, U, V
    const float* keys = (const float*)d_in[1];
    const float* U    = (const float*)d_in[3];
    const float* V    = (const float*)d_in[4];
    float* out = (float*)d_out;

    static int smem_set = 0;
    if (!smem_set) {
        cudaFuncSetAttribute(main_pass_kernel,
                             cudaFuncAttributeMaxDynamicSharedMemorySize,
                             SMEM_TOTAL);
        smem_set = 1;
    }

    vprime_fused_kernel<<<128, 256>>>(U, V);

    // main pass with PDL + dynamic smem
    cudaLaunchConfig_t cfg = {};
    cfg.gridDim  = dim3(NSB, BATCH, 1);
    cfg.blockDim = dim3(256, 1, 1);
    cfg.dynamicSmemBytes = SMEM_TOTAL;
    cudaLaunchAttribute attrs[1];
    attrs[0].id = cudaLaunchAttributeProgrammaticStreamSerialization;
    attrs[0].val.programmaticStreamSerializationAllowed = 1;
    cfg.attrs = attrs;
    cfg.numAttrs = 1;
    cudaLaunchKernelEx(&cfg, main_pass_kernel, keys, out);
}